// round 6
// baseline (speedup 1.0000x reference)
#include <cuda_runtime.h>
#include <math_constants.h>

// Problem dims (fixed for this instance)
#define N_  1024
#define M_  65536
#define D_  512
#define C_  10000
#define NREMOVE 512          // int(0.5 * 1024)

#define FLT_MIN_NORMAL 1.17549435e-38f

// -------- scratch (static __device__ globals: no runtime allocation) --------
__device__ float        g_logits[(size_t)N_ * C_];   // 40 MB, bss
__device__ float        g_Cval[N_];
__device__ unsigned int g_keep[N_];
__device__ double       g_pos, g_neg;

__global__ void k_init() { g_pos = 0.0; g_neg = 0.0; }

// ============================================================================
// Kernel 1: logits = inputs_col @ center^T in full f32.
// 128x128x16 tiles, 256 threads, 8x8 microtiles. Bounds-guard on C_ (10000).
// ============================================================================
__global__ __launch_bounds__(256) void k_logits(const float* __restrict__ A,
                                                const float* __restrict__ B) {
    __shared__ float As[16][128];
    __shared__ float Bs[16][128];

    const int tid = threadIdx.x;
    const int tx = tid % 16, ty = tid / 16;
    const int rowBase = blockIdx.y * 128;   // over N_
    const int colBase = blockIdx.x * 128;   // over C_

    float acc[8][8];
#pragma unroll
    for (int u = 0; u < 8; u++)
#pragma unroll
        for (int v = 0; v < 8; v++) acc[u][v] = 0.0f;

    for (int k0 = 0; k0 < D_; k0 += 16) {
#pragma unroll
        for (int r = 0; r < 2; r++) {
            int idx = tid + r * 256;
            int row = idx >> 2, kq = (idx & 3) * 4;
            float4 v = *(const float4*)(A + (size_t)(rowBase + row) * D_ + k0 + kq);
            As[kq + 0][row] = v.x; As[kq + 1][row] = v.y;
            As[kq + 2][row] = v.z; As[kq + 3][row] = v.w;
        }
#pragma unroll
        for (int r = 0; r < 2; r++) {
            int idx = tid + r * 256;
            int row = idx >> 2, kq = (idx & 3) * 4;
            int gc = colBase + row;
            float4 v = make_float4(0.f, 0.f, 0.f, 0.f);
            if (gc < C_) v = *(const float4*)(B + (size_t)gc * D_ + k0 + kq);
            Bs[kq + 0][row] = v.x; Bs[kq + 1][row] = v.y;
            Bs[kq + 2][row] = v.z; Bs[kq + 3][row] = v.w;
        }
        __syncthreads();
#pragma unroll
        for (int k = 0; k < 16; k++) {
            float a[8], b[8];
#pragma unroll
            for (int u = 0; u < 8; u++) a[u] = As[k][ty * 8 + u];
#pragma unroll
            for (int v = 0; v < 8; v++) b[v] = Bs[k][tx * 8 + v];
#pragma unroll
            for (int u = 0; u < 8; u++)
#pragma unroll
                for (int v = 0; v < 8; v++) acc[u][v] = fmaf(a[u], b[v], acc[u][v]);
        }
        __syncthreads();
    }

#pragma unroll
    for (int u = 0; u < 8; u++) {
        int gi = rowBase + ty * 8 + u;
#pragma unroll
        for (int v = 0; v < 8; v++) {
            int gc = colBase + tx * 8 + v;
            if (gc < C_) g_logits[(size_t)gi * C_ + gc] = acc[u][v];
        }
    }
}

// ============================================================================
// Kernel 2: per-row softmax target-prob with XLA-GPU FTZ semantics:
//   sel = expf(l_t - max) / sum(expf(l_c - max));  denormal sel -> 0.0f
// The FTZ flush creates the large exact-0.0 tie block (~534 rows > 512) that
// the reference's stable argsort resolves by index — the decisive behavior.
// ============================================================================
__global__ __launch_bounds__(256) void k_softmax_sel(const int* __restrict__ targets) {
    const int i = blockIdx.x;
    const float* row = g_logits + (size_t)i * C_;
    __shared__ float red[256];

    float mx = -CUDART_INF_F;
    for (int c = threadIdx.x; c < C_; c += 256) mx = fmaxf(mx, row[c]);
    red[threadIdx.x] = mx;
    __syncthreads();
    for (int s = 128; s > 0; s >>= 1) {
        if (threadIdx.x < s) red[threadIdx.x] = fmaxf(red[threadIdx.x], red[threadIdx.x + s]);
        __syncthreads();
    }
    mx = red[0];
    __syncthreads();

    float sum = 0.0f;
    for (int c = threadIdx.x; c < C_; c += 256) sum += expf(row[c] - mx);
    red[threadIdx.x] = sum;
    __syncthreads();
    for (int s = 128; s > 0; s >>= 1) {
        if (threadIdx.x < s) red[threadIdx.x] += red[threadIdx.x + s];
        __syncthreads();
    }

    if (threadIdx.x == 0) {
        int t = targets[i];
        float sel = expf(row[t] - mx) / red[0];
        if (sel < FLT_MIN_NORMAL) sel = 0.0f;   // FTZ: flush denormal result
        g_Cval[i] = sel;
    }
}

// ============================================================================
// Kernel 3: keep = remove the NREMOVE smallest C with stable tie-break.
// Key = (float_bits(C) << 32) | index (C >= 0 so bits are order-preserving);
// reproduces jnp.argsort's stable ordering exactly — including the index
// ordering inside the FTZ zero tie block.
// ============================================================================
__global__ __launch_bounds__(1024) void k_select() {
    __shared__ unsigned long long keys[N_];
    const int i = threadIdx.x;
    unsigned int b = __float_as_uint(g_Cval[i]);
    keys[i] = ((unsigned long long)b << 32) | (unsigned int)i;
    __syncthreads();
    unsigned long long me = keys[i];
    int rank = 0;
    for (int j = 0; j < N_; j++) rank += (keys[j] < me);
    g_keep[i] = (rank >= NREMOVE) ? 1u : 0u;
}

// ============================================================================
// Kernel 4: fused sim-GEMM + masked reduction (f32 FFMA; threshold sums are
// statistically insensitive to sim-precision differences vs the reference).
// ============================================================================
__global__ __launch_bounds__(256) void k_main(const float* __restrict__ A,
                                              const float* __restrict__ B,
                                              const int* __restrict__ tcol,
                                              const int* __restrict__ trow) {
    __shared__ float As[16][128];
    __shared__ float Bs[16][128];
    __shared__ int   sTr[128];
    __shared__ int   sTc[128];
    __shared__ unsigned int sK[128];
    __shared__ float redP[256], redN[256];

    const int tid = threadIdx.x;
    const int tx = tid % 16, ty = tid / 16;
    const int rowBase = blockIdx.y * 128;   // over N_
    const int colBase = blockIdx.x * 128;   // over M_

    if (tid < 128) {
        sTr[tid] = trow[colBase + tid];
    } else {
        int r = tid - 128;
        sTc[r] = tcol[rowBase + r];
        sK[r]  = g_keep[rowBase + r];
    }

    float acc[8][8];
#pragma unroll
    for (int u = 0; u < 8; u++)
#pragma unroll
        for (int v = 0; v < 8; v++) acc[u][v] = 0.0f;

    for (int k0 = 0; k0 < D_; k0 += 16) {
#pragma unroll
        for (int r = 0; r < 2; r++) {
            int idx = tid + r * 256;
            int row = idx >> 2, kq = (idx & 3) * 4;
            float4 v = *(const float4*)(A + (size_t)(rowBase + row) * D_ + k0 + kq);
            As[kq + 0][row] = v.x; As[kq + 1][row] = v.y;
            As[kq + 2][row] = v.z; As[kq + 3][row] = v.w;
        }
#pragma unroll
        for (int r = 0; r < 2; r++) {
            int idx = tid + r * 256;
            int row = idx >> 2, kq = (idx & 3) * 4;
            float4 v = *(const float4*)(B + (size_t)(colBase + row) * D_ + k0 + kq);
            Bs[kq + 0][row] = v.x; Bs[kq + 1][row] = v.y;
            Bs[kq + 2][row] = v.z; Bs[kq + 3][row] = v.w;
        }
        __syncthreads();
#pragma unroll
        for (int k = 0; k < 16; k++) {
            float a[8], b[8];
#pragma unroll
            for (int u = 0; u < 8; u++) a[u] = As[k][ty * 8 + u];
#pragma unroll
            for (int v = 0; v < 8; v++) b[v] = Bs[k][tx * 8 + v];
#pragma unroll
            for (int u = 0; u < 8; u++)
#pragma unroll
                for (int v = 0; v < 8; v++) acc[u][v] = fmaf(a[u], b[v], acc[u][v]);
        }
        __syncthreads();
    }

    const float ONE_MINUS_EPS = (float)(1.0 - 1e-5);
    const float MARGIN = 0.5f;
    float pos = 0.0f, neg = 0.0f;
#pragma unroll
    for (int u = 0; u < 8; u++) {
        int il = ty * 8 + u;
        if (!sK[il]) continue;
        int ti = sTc[il];
#pragma unroll
        for (int v = 0; v < 8; v++) {
            float s = acc[u][v];
            int rj = sTr[tx * 8 + v];
            if (ti == rj) {
                if (s < ONE_MINUS_EPS) pos += 1.0f - s;
            } else if (s > MARGIN) {
                neg += s;
            }
        }
    }

    redP[tid] = pos; redN[tid] = neg;
    __syncthreads();
    for (int s = 128; s > 0; s >>= 1) {
        if (tid < s) { redP[tid] += redP[tid + s]; redN[tid] += redN[tid + s]; }
        __syncthreads();
    }
    if (tid == 0) {
        atomicAdd(&g_pos, (double)redP[0]);
        atomicAdd(&g_neg, (double)redN[0]);
    }
}

// ============================================================================
// Kernel 5: finalize -> out[0] = loss, out[1..] = keep (0/1 floats)
// ============================================================================
__global__ void k_final(float* __restrict__ out, int out_size) {
    int i = blockIdx.x * blockDim.x + threadIdx.x;
    if (i >= out_size) return;
    if (i == 0) {
        out[0] = (float)((g_pos + g_neg) / (double)N_);
    } else {
        int k = i - 1;
        out[i] = (k < N_) ? (g_keep[k] ? 1.0f : 0.0f) : 0.0f;
    }
}

// ============================================================================
extern "C" void kernel_launch(void* const* d_in, const int* in_sizes, int n_in,
                              void* d_out, int out_size) {
    // Identify buffers by element count (all distinct) — immune to ordering.
    const float* inputs_col = nullptr;   // 1024*512   = 524288
    const float* inputs_row = nullptr;   // 65536*512  = 33554432
    const float* center     = nullptr;   // 10000*512  = 5120000
    const int*   targets_col = nullptr;  // 1024
    const int*   target_row  = nullptr;  // 65536
    for (int i = 0; i < n_in; i++) {
        switch (in_sizes[i]) {
            case 524288:   inputs_col  = (const float*)d_in[i]; break;
            case 33554432: inputs_row  = (const float*)d_in[i]; break;
            case 5120000:  center      = (const float*)d_in[i]; break;
            case 1024:     targets_col = (const int*)d_in[i];   break;
            case 65536:    target_row  = (const int*)d_in[i];   break;
            default: break; // 10000 = filled_mask (all True; unused)
        }
    }
    if (!inputs_col)  inputs_col  = (const float*)d_in[0];
    if (!inputs_row)  inputs_row  = (const float*)d_in[1];
    if (!center)      center      = (const float*)d_in[2];
    if (!targets_col) targets_col = (const int*)d_in[3];
    if (!target_row)  target_row  = (const int*)d_in[4];

    k_init<<<1, 1>>>();

    dim3 gA((C_ + 127) / 128, N_ / 128);
    k_logits<<<gA, 256>>>(inputs_col, center);

    k_softmax_sel<<<N_, 256>>>(targets_col);

    k_select<<<1, 1024>>>();

    dim3 gM(M_ / 128, N_ / 128);
    k_main<<<gM, 256>>>(inputs_col, inputs_row, targets_col, target_row);

    int threads = 256;
    int blocks = (out_size + threads - 1) / threads;
    if (blocks < 1) blocks = 1;
    k_final<<<blocks, threads>>>((float*)d_out, out_size);
}